// round 1
// baseline (speedup 1.0000x reference)
#include <cuda_runtime.h>
#include <cuda_bf16.h>

#define N_VAR 4194304
#define M_CHK 2097152
#define DC 10
#define CBLK 256

// scratch (device globals: allocation-free)
__device__ float g_v2c[N_VAR];
__device__ float g_acc[N_VAR];

// init: v2c = llr0 (iteration 1 of BP is identity since v2c0=0 -> c2v=0),
//       acc = llr0 (acc accumulates llr0 + vsum for the next round)
__global__ void bp_init(const float* __restrict__ llr0) {
    int i = blockIdx.x * blockDim.x + threadIdx.x;
    float4 v = reinterpret_cast<const float4*>(llr0)[i];
    reinterpret_cast<float4*>(g_v2c)[i] = v;
    reinterpret_cast<float4*>(g_acc)[i] = v;
}

// check-node update + scatter-add into acc
__global__ void __launch_bounds__(CBLK) bp_check(const int* __restrict__ adj,
                                                 const float* __restrict__ gamma_p) {
    __shared__ int s_adj[CBLK * DC];
    // coalesced vectorized stage of this block's adjacency rows
    const int4* gsrc = reinterpret_cast<const int4*>(adj + (size_t)blockIdx.x * (CBLK * DC));
    int4* sdst = reinterpret_cast<int4*>(s_adj);
    #pragma unroll
    for (int t = threadIdx.x; t < CBLK * DC / 4; t += CBLK) sdst[t] = gsrc[t];
    __syncthreads();

    const float gamma = __ldg(gamma_p);

    int idx[DC];
    #pragma unroll
    for (int j = 0; j < DC; j++) idx[j] = s_adj[threadIdx.x * DC + j];

    float mag = __int_as_float(0x7f800000);  // +inf
    unsigned sgn = 0u;
    #pragma unroll
    for (int j = 0; j < DC; j++) {
        // reference gathers raw -1 with numpy wrap -> index N-1
        int gi = (idx[j] < 0) ? (N_VAR - 1) : idx[j];
        float v = __ldg(&g_v2c[gi]);
        sgn ^= (__float_as_uint(v + 1e-12f) & 0x80000000u);
        mag = fminf(mag, fabsf(v));
    }
    float c2v = __uint_as_float(__float_as_uint(gamma * mag) ^ sgn);

    #pragma unroll
    for (int j = 0; j < DC; j++) {
        if (idx[j] >= 0) atomicAdd(&g_acc[idx[j]], c2v);
    }
}

// variable update: v2c = (llr0 + vsum) - v2c = acc - v2c ; reset acc = llr0
__global__ void bp_update(const float* __restrict__ llr0) {
    int i = blockIdx.x * blockDim.x + threadIdx.x;
    float4 a = reinterpret_cast<float4*>(g_acc)[i];
    float4 v = reinterpret_cast<float4*>(g_v2c)[i];
    float4 l = reinterpret_cast<const float4*>(llr0)[i];
    float4 nv = make_float4(a.x - v.x, a.y - v.y, a.z - v.z, a.w - v.w);
    reinterpret_cast<float4*>(g_v2c)[i] = nv;
    reinterpret_cast<float4*>(g_acc)[i] = l;
}

// final: out = llr0 + v2c_final = llr0 + (acc - v2c)
__global__ void bp_final(const float* __restrict__ llr0, float* __restrict__ out) {
    int i = blockIdx.x * blockDim.x + threadIdx.x;
    float4 a = reinterpret_cast<float4*>(g_acc)[i];
    float4 v = reinterpret_cast<float4*>(g_v2c)[i];
    float4 l = reinterpret_cast<const float4*>(llr0)[i];
    float4 o = make_float4(l.x + a.x - v.x, l.y + a.y - v.y,
                           l.z + a.z - v.z, l.w + a.w - v.w);
    reinterpret_cast<float4*>(out)[i] = o;
}

extern "C" void kernel_launch(void* const* d_in, const int* in_sizes, int n_in,
                              void* d_out, int out_size) {
    const float* llr0  = (const float*)d_in[0];
    const float* gamma = (const float*)d_in[1];
    const int*   adj   = (const int*)d_in[2];
    // d_in[3] = n_iter (always 5 per problem setup)
    float* out = (float*)d_out;

    const int vec_blocks = N_VAR / 4 / 256;   // float4-wide elementwise kernels
    const int chk_blocks = M_CHK / CBLK;

    bp_init<<<vec_blocks, 256>>>(llr0);
    // n_iter = 5; iteration 1 is exact identity (v2c0 = 0 -> c2v = 0 -> v2c1 = llr0),
    // so run 4 real check/update rounds.
    for (int t = 0; t < 4; t++) {
        bp_check<<<chk_blocks, CBLK>>>(adj, gamma);
        if (t < 3) bp_update<<<vec_blocks, 256>>>(llr0);
        else       bp_final<<<vec_blocks, 256>>>(llr0, out);
    }
}

// round 2
// speedup vs baseline: 1.0175x; 1.0175x over previous
#include <cuda_runtime.h>
#include <cuda_bf16.h>
#include <cstdint>

#define N_VAR 4194304
#define M_CHK 2097152
#define DC 10
#define CBLK 256
#define ADJ_BYTES (CBLK * DC * 4)

// scratch (device globals: allocation-free)
__device__ float g_b0[N_VAR];
__device__ float g_b1[N_VAR];
__device__ float g_b2[N_VAR];

__device__ __forceinline__ uint32_t smem_u32(const void* p) {
    uint32_t a;
    asm("{ .reg .u64 t; cvta.to.shared.u64 t, %1; cvt.u32.u64 %0, t; }" : "=r"(a) : "l"(p));
    return a;
}

// zero both accumulator buffers up front
__global__ void bp_zero() {
    int i = blockIdx.x * blockDim.x + threadIdx.x;
    float4 z = make_float4(0.f, 0.f, 0.f, 0.f);
    reinterpret_cast<float4*>(g_b0)[i] = z;
    reinterpret_cast<float4*>(g_b1)[i] = z;
}

// check-node update: gather src, min-sum, scatter-add into dst (dst pre-zeroed
// or pre-seeded). adj rows staged to smem via TMA bulk copy (no LSU lanes).
__global__ void __launch_bounds__(CBLK) bp_check(const int* __restrict__ adj,
                                                 const float* __restrict__ gamma_p,
                                                 const float* __restrict__ src,
                                                 float* __restrict__ dst) {
    __shared__ __align__(16) int s_adj[CBLK * DC];
    __shared__ __align__(8) unsigned long long s_mbar;

    const int tid = threadIdx.x;
    uint32_t mbar = smem_u32(&s_mbar);
    uint32_t sdst = smem_u32(s_adj);

    if (tid == 0) {
        asm volatile("mbarrier.init.shared.b64 [%0], 1;" :: "r"(mbar) : "memory");
    }
    __syncthreads();
    if (tid == 0) {
        asm volatile("mbarrier.arrive.expect_tx.shared.b64 _, [%0], %1;"
                     :: "r"(mbar), "r"((uint32_t)ADJ_BYTES) : "memory");
        const int* gsrc = adj + (size_t)blockIdx.x * (CBLK * DC);
        asm volatile(
            "cp.async.bulk.shared::cta.global.mbarrier::complete_tx::bytes "
            "[%0], [%1], %2, [%3];"
            :: "r"(sdst), "l"(gsrc), "r"((uint32_t)ADJ_BYTES), "r"(mbar) : "memory");
    }
    // wait for TMA completion (phase 0)
    {
        uint32_t done;
        asm volatile(
            "{\n\t.reg .pred p;\n\t"
            "mbarrier.try_wait.parity.acquire.cta.shared::cta.b64 p, [%1], 0;\n\t"
            "selp.b32 %0, 1, 0, p;\n\t}"
            : "=r"(done) : "r"(mbar) : "memory");
        while (!done) {
            asm volatile(
                "{\n\t.reg .pred p;\n\t"
                "mbarrier.try_wait.parity.acquire.cta.shared::cta.b64 p, [%1], 0, 0x989680;\n\t"
                "selp.b32 %0, 1, 0, p;\n\t}"
                : "=r"(done) : "r"(mbar) : "memory");
        }
    }

    const float gamma = __ldg(gamma_p);
    const float vlast = __ldg(&src[N_VAR - 1]);  // broadcast: all padded (-1) slots wrap here

    int idx[DC];
    #pragma unroll
    for (int j = 0; j < DC; j++) idx[j] = s_adj[tid * DC + j];

    float mag = __int_as_float(0x7f800000);  // +inf
    unsigned sgn = 0u;
    #pragma unroll
    for (int j = 0; j < DC; j++) {
        float v = (idx[j] >= 0) ? __ldg(&src[idx[j]]) : vlast;
        sgn ^= (__float_as_uint(v + 1e-12f) & 0x80000000u);
        mag = fminf(mag, fabsf(v));
    }
    float c2v = __uint_as_float(__float_as_uint(gamma * mag) ^ sgn);

    #pragma unroll
    for (int j = 0; j < DC; j++) {
        if (idx[j] >= 0) atomicAdd(&dst[idx[j]], c2v);
    }
}

// v2c_next = llr0 + vsum - v2c_prev; also zero the buffer that becomes the
// next accumulator (zbuf).
__global__ void bp_update(const float* __restrict__ llr0,
                          const float* __restrict__ vsum,
                          const float* __restrict__ v2c_prev,
                          float* __restrict__ v2c_next,
                          float* __restrict__ zbuf) {
    int i = blockIdx.x * blockDim.x + threadIdx.x;
    float4 l = reinterpret_cast<const float4*>(llr0)[i];
    float4 s = reinterpret_cast<const float4*>(vsum)[i];
    float4 p = reinterpret_cast<const float4*>(v2c_prev)[i];
    float4 nv = make_float4(l.x + s.x - p.x, l.y + s.y - p.y,
                            l.z + s.z - p.z, l.w + s.w - p.w);
    reinterpret_cast<float4*>(v2c_next)[i] = nv;
    reinterpret_cast<float4*>(zbuf)[i] = make_float4(0.f, 0.f, 0.f, 0.f);
}

// out = llr0 + v2c5 = llr0 + (llr0 + vsum5 - v2c4) = 2*llr0 + vsum5 - v2c4
__global__ void bp_final(const float* __restrict__ llr0,
                         const float* __restrict__ vsum5,
                         const float* __restrict__ v2c4,
                         float* __restrict__ out) {
    int i = blockIdx.x * blockDim.x + threadIdx.x;
    float4 l = reinterpret_cast<const float4*>(llr0)[i];
    float4 s = reinterpret_cast<const float4*>(vsum5)[i];
    float4 p = reinterpret_cast<const float4*>(v2c4)[i];
    float4 o = make_float4(2.f * l.x + s.x - p.x, 2.f * l.y + s.y - p.y,
                           2.f * l.z + s.z - p.z, 2.f * l.w + s.w - p.w);
    reinterpret_cast<float4*>(out)[i] = o;
}

extern "C" void kernel_launch(void* const* d_in, const int* in_sizes, int n_in,
                              void* d_out, int out_size) {
    const float* llr0  = (const float*)d_in[0];
    const float* gamma = (const float*)d_in[1];
    const int*   adj   = (const int*)d_in[2];
    float* out = (float*)d_out;

    float *b0, *b1, *b2;
    cudaGetSymbolAddress((void**)&b0, g_b0);
    cudaGetSymbolAddress((void**)&b1, g_b1);
    cudaGetSymbolAddress((void**)&b2, g_b2);

    const int vec_blocks = N_VAR / 4 / 256;
    const int chk_blocks = M_CHK / CBLK;

    // n_iter = 5. Iter 1 is identity (v2c1 = llr0). Iter 2 gathers llr0 and
    // its vsum2 IS v2c2 (llr0 + vsum2 - llr0), so no init/update needed.
    bp_zero<<<vec_blocks, 256>>>();
    // iter 2: gather llr0, accumulate into b0 -> b0 = vsum2 = v2c2
    bp_check<<<chk_blocks, CBLK>>>(adj, gamma, llr0, b0);
    // iter 3: gather v2c2 (b0), accumulate into b1 -> b1 = vsum3
    bp_check<<<chk_blocks, CBLK>>>(adj, gamma, b0, b1);
    // v2c3 = llr0 + b1 - b0 -> b2 ; zero b0 for next accumulator
    bp_update<<<vec_blocks, 256>>>(llr0, b1, b0, b2, b0);
    // iter 4: gather v2c3 (b2), accumulate into b0 -> b0 = vsum4
    bp_check<<<chk_blocks, CBLK>>>(adj, gamma, b2, b0);
    // v2c4 = llr0 + b0 - b2 -> b1 ; zero b2 for next accumulator
    bp_update<<<vec_blocks, 256>>>(llr0, b0, b2, b1, b2);
    // iter 5: gather v2c4 (b1), accumulate into b2 -> b2 = vsum5
    bp_check<<<chk_blocks, CBLK>>>(adj, gamma, b1, b2);
    // out = 2*llr0 + vsum5 - v2c4
    bp_final<<<vec_blocks, 256>>>(llr0, b2, b1, out);
}

// round 3
// speedup vs baseline: 1.0273x; 1.0096x over previous
#include <cuda_runtime.h>
#include <cuda_bf16.h>
#include <cstdint>

#define N_VAR 4194304
#define M_CHK 2097152
#define DC 10
#define CBLK 256
#define ADJ_BYTES (CBLK * DC * 4)

// scratch (device globals: allocation-free)
__device__ float g_b0[N_VAR];
__device__ float g_b1[N_VAR];
__device__ float g_b2[N_VAR];

__device__ __forceinline__ uint32_t smem_u32(const void* p) {
    uint32_t a;
    asm("{ .reg .u64 t; cvta.to.shared.u64 t, %1; cvt.u32.u64 %0, t; }" : "=r"(a) : "l"(p));
    return a;
}

// seed accumulator with zero
__global__ void bp_seed_zero(float* __restrict__ acc) {
    int i = blockIdx.x * blockDim.x + threadIdx.x;
    reinterpret_cast<float4*>(acc)[i] = make_float4(0.f, 0.f, 0.f, 0.f);
}

// seed accumulator: acc = scale*llr0 - v2c_prev  (scale = 1 for mid iterations,
// 2 for the final iteration where acc IS the output buffer)
__global__ void bp_seed(const float* __restrict__ llr0,
                        const float* __restrict__ v2c_prev,
                        float* __restrict__ acc, float scale) {
    int i = blockIdx.x * blockDim.x + threadIdx.x;
    float4 l = reinterpret_cast<const float4*>(llr0)[i];
    float4 p = reinterpret_cast<const float4*>(v2c_prev)[i];
    float4 s = make_float4(fmaf(scale, l.x, -p.x), fmaf(scale, l.y, -p.y),
                           fmaf(scale, l.z, -p.z), fmaf(scale, l.w, -p.w));
    reinterpret_cast<float4*>(acc)[i] = s;
}

// check-node update: gather src, min-sum, scatter-add into pre-seeded dst.
// adj rows staged to smem via TMA bulk copy (keeps LSU lanes for gathers/REDs).
__global__ void __launch_bounds__(CBLK) bp_check(const int* __restrict__ adj,
                                                 const float* __restrict__ gamma_p,
                                                 const float* __restrict__ src,
                                                 float* __restrict__ dst) {
    __shared__ __align__(16) int s_adj[CBLK * DC];
    __shared__ __align__(8) unsigned long long s_mbar;

    const int tid = threadIdx.x;
    uint32_t mbar = smem_u32(&s_mbar);
    uint32_t sdst = smem_u32(s_adj);

    if (tid == 0) {
        asm volatile("mbarrier.init.shared.b64 [%0], 1;" :: "r"(mbar) : "memory");
    }
    __syncthreads();
    if (tid == 0) {
        asm volatile("mbarrier.arrive.expect_tx.shared.b64 _, [%0], %1;"
                     :: "r"(mbar), "r"((uint32_t)ADJ_BYTES) : "memory");
        const int* gsrc = adj + (size_t)blockIdx.x * (CBLK * DC);
        asm volatile(
            "cp.async.bulk.shared::cta.global.mbarrier::complete_tx::bytes "
            "[%0], [%1], %2, [%3];"
            :: "r"(sdst), "l"(gsrc), "r"((uint32_t)ADJ_BYTES), "r"(mbar) : "memory");
    }
    // wait for TMA completion (phase 0)
    {
        uint32_t done;
        asm volatile(
            "{\n\t.reg .pred p;\n\t"
            "mbarrier.try_wait.parity.acquire.cta.shared::cta.b64 p, [%1], 0;\n\t"
            "selp.b32 %0, 1, 0, p;\n\t}"
            : "=r"(done) : "r"(mbar) : "memory");
        while (!done) {
            asm volatile(
                "{\n\t.reg .pred p;\n\t"
                "mbarrier.try_wait.parity.acquire.cta.shared::cta.b64 p, [%1], 0, 0x989680;\n\t"
                "selp.b32 %0, 1, 0, p;\n\t}"
                : "=r"(done) : "r"(mbar) : "memory");
        }
    }

    const float gamma = __ldg(gamma_p);
    const float vlast = __ldg(&src[N_VAR - 1]);  // all padded (-1) slots wrap here

    int idx[DC];
    #pragma unroll
    for (int j = 0; j < DC; j++) idx[j] = s_adj[tid * DC + j];

    float mag = __int_as_float(0x7f800000);  // +inf
    unsigned sgn = 0u;
    #pragma unroll
    for (int j = 0; j < DC; j++) {
        float v = (idx[j] >= 0) ? __ldg(&src[idx[j]]) : vlast;
        sgn ^= (__float_as_uint(v + 1e-12f) & 0x80000000u);
        mag = fminf(mag, fabsf(v));
    }
    float c2v = __uint_as_float(__float_as_uint(gamma * mag) ^ sgn);

    #pragma unroll
    for (int j = 0; j < DC; j++) {
        if (idx[j] >= 0) atomicAdd(&dst[idx[j]], c2v);
    }
}

extern "C" void kernel_launch(void* const* d_in, const int* in_sizes, int n_in,
                              void* d_out, int out_size) {
    const float* llr0  = (const float*)d_in[0];
    const float* gamma = (const float*)d_in[1];
    const int*   adj   = (const int*)d_in[2];
    float* out = (float*)d_out;

    float *b0, *b1, *b2;
    cudaGetSymbolAddress((void**)&b0, g_b0);
    cudaGetSymbolAddress((void**)&b1, g_b1);
    cudaGetSymbolAddress((void**)&b2, g_b2);

    const int vec_blocks = N_VAR / 4 / 256;
    const int chk_blocks = M_CHK / CBLK;

    // n_iter = 5. Iter 1 is exact identity (v2c1 = llr0). Remaining 4 rounds:
    // accumulators are pre-seeded with (llr0 - v2c_prev) so the check kernel's
    // atomics produce v2c_next in place; the final accumulator is d_out itself,
    // seeded with (2*llr0 - v2c_4) so out = llr0 + v2c_5 directly.
    bp_seed_zero<<<vec_blocks, 256>>>(b0);                 // seed iter2 (llr0 - llr0 = 0)
    bp_check<<<chk_blocks, CBLK>>>(adj, gamma, llr0, b0);  // b0 = v2c_2
    bp_seed<<<vec_blocks, 256>>>(llr0, b0, b1, 1.f);       // b1 = llr0 - v2c_2
    bp_check<<<chk_blocks, CBLK>>>(adj, gamma, b0, b1);    // b1 = v2c_3
    bp_seed<<<vec_blocks, 256>>>(llr0, b1, b2, 1.f);       // b2 = llr0 - v2c_3
    bp_check<<<chk_blocks, CBLK>>>(adj, gamma, b1, b2);    // b2 = v2c_4
    bp_seed<<<vec_blocks, 256>>>(llr0, b2, out, 2.f);      // out = 2*llr0 - v2c_4
    bp_check<<<chk_blocks, CBLK>>>(adj, gamma, b2, out);   // out = llr0 + v2c_5
}